// round 14
// baseline (speedup 1.0000x reference)
#include <cuda_runtime.h>
#include <math.h>

#define VOCAB 50000
#define EMBD  256
#define HID   512
#define BSZ   64
#define SEQ   1024
#define NCTA  96
#define NCTA_A 32
#define TPB   512

// ---------------- device-global scratch (no allocation APIs used) ----------------
__device__ float g_P[VOCAB * HID];          // projected embedding + layer0 biases (102.4 MB)
__device__ float g_H[2][1024 * BSZ];        // double-buffered [h0(512 rows); h1(512 rows)] x [64 b]
__device__ unsigned g_bar_count;            // grid barrier counter (returns to 0 each barrier)
__device__ unsigned g_bar_gen;              // monotonic generation (graph-replay safe)

typedef unsigned long long ull;

// ---------------- f32x2 helpers (FFMA2 reachable only via PTX) ----------------
__device__ __forceinline__ ull pk2(float x, float y) {
    ull r; asm("mov.b64 %0,{%1,%2};" : "=l"(r) : "f"(x), "f"(y)); return r;
}
__device__ __forceinline__ void upk2(ull v, float& x, float& y) {
    asm("mov.b64 {%0,%1},%2;" : "=f"(x), "=f"(y) : "l"(v));
}
__device__ __forceinline__ void fma2(ull& d, ull a, ull b) {
    asm("fma.rn.f32x2 %0,%1,%2,%0;" : "+l"(d) : "l"(a), "l"(b));
}
__device__ __forceinline__ ull add2(ull a, ull b) {
    ull r; asm("add.rn.f32x2 %0,%1,%2;" : "=l"(r) : "l"(a), "l"(b)); return r;
}

// ---------------- grid barrier (all NCTA CTAs co-resident: 1 CTA/SM, 96 <= 148) ----------------
__device__ __forceinline__ void grid_barrier() {
    __threadfence();          // release this CTA's global writes
    __syncthreads();
    if (threadIdx.x == 0) {
        volatile unsigned* vgen = &g_bar_gen;
        unsigned g = *vgen;   // read generation BEFORE arriving
        unsigned a = atomicAdd(&g_bar_count, 1u);
        if (a == NCTA - 1u) {
            atomicExch(&g_bar_count, 0u);   // reset count first
            __threadfence();
            *vgen = g + 1u;                 // open next generation
        } else {
            while (*vgen == g) { }          // tight poll: wakeup ~ one L2 read
        }
        __threadfence();                    // acquire other CTAs' writes
    }
    __syncthreads();
}

// ---------------- kernel 1: P[v][j] = sum_k emb[v][k]*Wxh0[k][j] + bxh0[j] + bhh0[j] ----------------
__global__ __launch_bounds__(256) void proj_kernel(
    const float* __restrict__ emb, const float* __restrict__ Wxh0,
    const float* __restrict__ bxh0, const float* __restrict__ bhh0)
{
    __shared__ float As[16][136];   // [k][m], padded
    __shared__ float Bs[16][136];   // [k][n], padded
    const int tid = threadIdx.x;
    const int bm = blockIdx.y * 128;
    const int bn = blockIdx.x * 128;
    const int tx = tid & 15;        // n tile (8 cols each)
    const int ty = tid >> 4;        // m tile (8 rows each)

    ull acc2[8][4];                 // 8 m-rows x 4 n-pairs, f32x2 accumulators
    #pragma unroll
    for (int i = 0; i < 8; ++i)
        #pragma unroll
        for (int j = 0; j < 4; ++j) acc2[i][j] = 0ULL;

    for (int k0 = 0; k0 < EMBD; k0 += 16) {
        #pragma unroll
        for (int q = 0; q < 2; ++q) {
            int idx = tid + q * 256;          // 0..511
            int m  = idx >> 2;
            int kq = (idx & 3) * 4;
            int gm = bm + m;
            float4 e = make_float4(0.f, 0.f, 0.f, 0.f);
            if (gm < VOCAB) e = *reinterpret_cast<const float4*>(&emb[gm * EMBD + k0 + kq]);
            As[kq + 0][m] = e.x; As[kq + 1][m] = e.y; As[kq + 2][m] = e.z; As[kq + 3][m] = e.w;
        }
        #pragma unroll
        for (int q = 0; q < 2; ++q) {
            int idx = tid + q * 256;
            int kk = idx >> 5;
            int j4 = (idx & 31) * 4;
            *reinterpret_cast<float4*>(&Bs[kk][j4]) =
                *reinterpret_cast<const float4*>(&Wxh0[(k0 + kk) * HID + bn + j4]);
        }
        __syncthreads();
        #pragma unroll
        for (int kk = 0; kk < 16; ++kk) {
            float4 a0 = *reinterpret_cast<const float4*>(&As[kk][ty * 8]);
            float4 a1 = *reinterpret_cast<const float4*>(&As[kk][ty * 8 + 4]);
            ulonglong2 b0 = *reinterpret_cast<const ulonglong2*>(&Bs[kk][tx * 8]);
            ulonglong2 b1 = *reinterpret_cast<const ulonglong2*>(&Bs[kk][tx * 8 + 4]);
            float am[8] = {a0.x, a0.y, a0.z, a0.w, a1.x, a1.y, a1.z, a1.w};
            ull bp[4] = {b0.x, b0.y, b1.x, b1.y};
            #pragma unroll
            for (int i = 0; i < 8; ++i) {
                ull ai = pk2(am[i], am[i]);
                #pragma unroll
                for (int j = 0; j < 4; ++j) fma2(acc2[i][j], ai, bp[j]);
            }
        }
        __syncthreads();
    }

    float bj[8];
    #pragma unroll
    for (int j = 0; j < 8; ++j) {
        int jg = bn + tx * 8 + j;
        bj[j] = __ldg(&bxh0[jg]) + __ldg(&bhh0[jg]);
    }
    #pragma unroll
    for (int i = 0; i < 8; ++i) {
        int gm = bm + ty * 8 + i;
        if (gm < VOCAB) {
            float o[8];
            #pragma unroll
            for (int j = 0; j < 4; ++j) upk2(acc2[i][j], o[2 * j], o[2 * j + 1]);
            float4 o0 = make_float4(o[0] + bj[0], o[1] + bj[1], o[2] + bj[2], o[3] + bj[3]);
            float4 o1 = make_float4(o[4] + bj[4], o[5] + bj[5], o[6] + bj[6], o[7] + bj[7]);
            *reinterpret_cast<float4*>(&g_P[gm * HID + bn + tx * 8])     = o0;
            *reinterpret_cast<float4*>(&g_P[gm * HID + bn + tx * 8 + 4]) = o1;
        }
    }
}

// ---------------- per-CTA phase worker (512 threads) ----------------
// ISA=true : job A — h0(p) = tanh(P[x[b,p]] + h0(p-1) @ Whh0).  32 CTAs: 2 b-tiles(32) x 16 j-tiles(32).
// ISA=false: job B — h1(p-1) = tanh([h0(p-1);h1(p-2)] @ [Wxh1;Whh1] + b). 64 CTAs: 4 b-tiles(16) x 16 j-tiles(32).
template <bool ISA>
__device__ __forceinline__ void run_cta(
    float* __restrict__ Wsm, float* __restrict__ HR, int cid,
    const int* __restrict__ xtok,
    const float* __restrict__ Whh0, const float* __restrict__ Wxh1, const float* __restrict__ Whh1,
    const float* __restrict__ bxh1, const float* __restrict__ bhh1)
{
    constexpr int BB     = ISA ? 32 : 16;       // batch cols per CTA
    constexpr int KTOT   = ISA ? 512 : 1024;    // dot length
    constexpr int KT_EFF = 16;                  // k-groups AFTER warp pre-reduction
    constexpr int NBT    = ISA ? 4 : 2;         // b-tiles of 8 per CTA
    constexpr int NOUT   = 32 * BB;             // outputs per CTA (1024 / 512)
    constexpr int STRIDE = NOUT + 8;            // padded reduction row
    constexpr int NI     = NOUT / TPB;          // outputs per thread in stage-2 (A:2, B:1)
    constexpr int SH     = ISA ? 8 : 7;         // (o >> SH)&3 recovers jt

    const int tid = threadIdx.x;
    const int b0  = ISA ? (cid & 1) * 32 : (cid & 3) * 16;
    const int j0  = ISA ? (cid >> 1) * 32 : (cid >> 2) * 32;

    const int jt  = tid & 3;
    const int bt  = (tid >> 2) & (NBT - 1);
    const int kt  = ISA ? (tid >> 4) : (tid >> 3);   // A:0..31, B:0..63 (k-slice = 16)
    const int wrp = tid >> 5;                        // effective k-group after shuffle reduce
    const int jl0 = jt * 8;
    const int bl0 = bt * 8;
    const int ks  = kt * 16;
    const bool writer = ISA ? (((tid >> 4) & 1) == 0) : (((tid >> 3) & 3) == 0);

    // ---- load weights into SMEM once (constant across all phases) ----
    #pragma unroll
    for (int i = 0; i < KTOT / 64; ++i) {
        int idx = tid + i * TPB;
        int k   = idx >> 3;
        int c4  = (idx & 7) << 2;
        const float* src;
        if (ISA) src = &Whh0[k * HID + j0 + c4];
        else     src = (k < 512) ? &Wxh1[k * HID + j0 + c4] : &Whh1[(k - 512) * HID + j0 + c4];
        float4 v = *reinterpret_cast<const float4*>(src);
        int sw = (k & 16) ? 4 : 0;    // XOR-4 swizzle keyed on k&16 (warp kt-neighbors differ by 16)
        *reinterpret_cast<float4*>(&Wsm[k * 32 + (c4 ^ sw)]) = v;
    }

    for (int p = 0; p <= SEQ; ++p) {
        const float* Hc = &g_H[p & 1][0];
        float*       Hn = &g_H[(p & 1) ^ 1][0];

        // ---- stage state slice into SMEM (L2-coherent reads: L1 stale across grid barrier) ----
        #pragma unroll
        for (int i = 0; i < 8; ++i) {
            int idx = tid + i * TPB;
            int k, c4;
            if (ISA) { k = idx >> 3; c4 = (idx & 7) << 2; }
            else     { k = idx >> 2; c4 = (idx & 3) << 2; }
            float4 v = __ldcg(reinterpret_cast<const float4*>(&Hc[k * 64 + b0 + c4]));
            int sw = (k & 16) ? 4 : 0;
            *reinterpret_cast<float4*>(&HR[k * BB + (c4 ^ sw)]) = v;
        }
        __syncthreads();

        // ---- compute: 8j x 8b tile over k-slice of 16, f32x2 FMAs ----
        ull acc[4][8];
        #pragma unroll
        for (int a = 0; a < 4; ++a)
            #pragma unroll
            for (int b = 0; b < 8; ++b) acc[a][b] = 0ULL;

        #pragma unroll
        for (int kk = 0; kk < 16; ++kk) {
            int k  = ks + kk;
            int sw = (k & 16) ? 4 : 0;
            ulonglong2 wlo = *reinterpret_cast<const ulonglong2*>(&Wsm[k * 32 + (jl0 ^ sw)]);
            ulonglong2 whi = *reinterpret_cast<const ulonglong2*>(&Wsm[k * 32 + ((jl0 + 4) ^ sw)]);
            float4 ha  = *reinterpret_cast<const float4*>(&HR[k * BB + (bl0 ^ sw)]);
            float4 hb4 = *reinterpret_cast<const float4*>(&HR[k * BB + ((bl0 + 4) ^ sw)]);
            ull hb[8];
            hb[0] = pk2(ha.x, ha.x);   hb[1] = pk2(ha.y, ha.y);
            hb[2] = pk2(ha.z, ha.z);   hb[3] = pk2(ha.w, ha.w);
            hb[4] = pk2(hb4.x, hb4.x); hb[5] = pk2(hb4.y, hb4.y);
            hb[6] = pk2(hb4.z, hb4.z); hb[7] = pk2(hb4.w, hb4.w);
            #pragma unroll
            for (int b = 0; b < 8; ++b) {
                fma2(acc[0][b], wlo.x, hb[b]);
                fma2(acc[1][b], wlo.y, hb[b]);
                fma2(acc[2][b], whi.x, hb[b]);
                fma2(acc[3][b], whi.y, hb[b]);
            }
        }

        // ---- warp pre-reduction over kt-neighbors (keeps split-K buffer at 16 groups) ----
        #pragma unroll
        for (int a = 0; a < 4; ++a)
            #pragma unroll
            for (int b = 0; b < 8; ++b) {
                if (!ISA) acc[a][b] = add2(acc[a][b], __shfl_xor_sync(0xFFFFFFFFu, acc[a][b], 8));
                acc[a][b] = add2(acc[a][b], __shfl_xor_sync(0xFFFFFFFFu, acc[a][b], 16));
            }

        __syncthreads();   // everyone done reading HR before it becomes the reduction buffer

        // ---- stage-1: write split-K partials (swizzled: conflict-free) ----
        if (writer) {
            int rb = wrp * STRIDE + 2 * jt + (wrp & 1);
            #pragma unroll
            for (int a = 0; a < 4; ++a) {
                int jl = jl0 + 2 * a;
                #pragma unroll
                for (int b = 0; b < 8; ++b) {
                    float lo, hi;
                    upk2(acc[a][b], lo, hi);
                    HR[rb + jl * BB + bl0 + b]       = lo;
                    HR[rb + (jl + 1) * BB + bl0 + b] = hi;
                }
            }
        }
        __syncthreads();

        // ---- stage-2: reduce over KT_EFF, fuse epilogue (gather/bias + tanh), coalesced store ----
        #pragma unroll
        for (int i = 0; i < NI; ++i) {
            int o   = tid + i * TPB;
            int off = o + 2 * ((o >> SH) & 3);
            float s = 0.f;
            #pragma unroll
            for (int q = 0; q < KT_EFF; ++q)
                s += HR[q * STRIDE + off + (q & 1)];
            int jl = ISA ? (o >> 5) : (o >> 4);
            int bl = o & (BB - 1);
            int jg = j0 + jl;
            int bg = b0 + bl;
            if (ISA) {
                if (p < SEQ) {
                    int tok = __ldg(&xtok[bg * SEQ + p]);
                    Hn[jg * 64 + bg] = tanhf(s + __ldg(&g_P[tok * HID + jg]));
                }
            } else {
                if (p >= 1) {
                    Hn[(512 + jg) * 64 + bg] = tanhf(s + __ldg(&bxh1[jg]) + __ldg(&bhh1[jg]));
                }
            }
        }
        grid_barrier();
    }
}

// ---------------- kernel 2: persistent pipelined RNN ----------------
__global__ __launch_bounds__(TPB, 1) void rnn_kernel(
    const int* __restrict__ x,
    const float* __restrict__ Whh0,
    const float* __restrict__ Wxh1, const float* __restrict__ Whh1,
    const float* __restrict__ bxh1, const float* __restrict__ bhh1,
    const float* __restrict__ fc_w, const float* __restrict__ fc_b,
    float* __restrict__ out)
{
    extern __shared__ float smem[];

    // zero-init both state buffers (h0(-1)=0, h1(-1)=h1(-2)=0)
    for (int i = blockIdx.x * TPB + threadIdx.x; i < 2 * 1024 * BSZ; i += NCTA * TPB)
        (&g_H[0][0])[i] = 0.f;
    grid_barrier();

    if (blockIdx.x < NCTA_A) {
        float* Wsm = smem;                 // 512*32 floats (64 KB)
        float* HR  = smem + 512 * 32;      // max(16384 staging, 16*1032 stage1) = 16512 floats
        run_cta<true>(Wsm, HR, blockIdx.x, x, Whh0, Wxh1, Whh1, bxh1, bhh1);
    } else {
        float* Wsm = smem;                 // 1024*32 floats (128 KB)
        float* HR  = smem + 1024 * 32;     // max(16384 staging, 16*520 stage1) = 16384 floats
        run_cta<false>(Wsm, HR, blockIdx.x - NCTA_A, x, Whh0, Wxh1, Whh1, bxh1, bhh1);
    }

    // ---- final: out[b] = sigmoid(h1(S-1) . fc_w + fc_b) ; h1(S-1) sits in g_H[1] rows 512+ ----
    if (blockIdx.x == 0 && threadIdx.x < 256) {
        float* red = smem + 512 * 32;     // A-type CTA, HR region free now
        int tid = threadIdx.x;
        int b = tid >> 2, q = tid & 3;
        const float* h1 = &g_H[1][512 * 64];
        float s = 0.f;
        for (int j = q * 128; j < q * 128 + 128; ++j)
            s += __ldcg(&h1[j * 64 + b]) * __ldg(&fc_w[j]);
        red[tid] = s;
        __syncwarp();
        __threadfence_block();
        if (q == 0) {
            float z = red[tid] + red[tid + 1] + red[tid + 2] + red[tid + 3] + __ldg(&fc_b[0]);
            out[b] = 1.f / (1.f + expf(-z));
        }
    }
}

// ---------------- launch ----------------
#define RNN_SMEM ((1024 * 32 + 16512) * (int)sizeof(float))   // 197184 B

extern "C" void kernel_launch(void* const* d_in, const int* in_sizes, int n_in,
                              void* d_out, int out_size)
{
    const int*   x    = (const int*)  d_in[0];
    const float* emb  = (const float*)d_in[1];
    const float* Wxh0 = (const float*)d_in[2];
    const float* bxh0 = (const float*)d_in[3];
    const float* Whh0 = (const float*)d_in[4];
    const float* bhh0 = (const float*)d_in[5];
    const float* Wxh1 = (const float*)d_in[6];
    const float* bxh1 = (const float*)d_in[7];
    const float* Whh1 = (const float*)d_in[8];
    const float* bhh1 = (const float*)d_in[9];
    const float* fc_w = (const float*)d_in[10];
    const float* fc_b = (const float*)d_in[11];
    float* out = (float*)d_out;

    cudaFuncSetAttribute(rnn_kernel, cudaFuncAttributeMaxDynamicSharedMemorySize, RNN_SMEM);

    dim3 gp(HID / 128, (VOCAB + 127) / 128);   // 4 x 391
    proj_kernel<<<gp, 256>>>(emb, Wxh0, bxh0, bhh0);
    rnn_kernel<<<NCTA, TPB, RNN_SMEM>>>(x, Whh0, Wxh1, Whh1, bxh1, bhh1, fc_w, fc_b, out);
}

// round 15
// speedup vs baseline: 1.1051x; 1.1051x over previous
#include <cuda_runtime.h>
#include <math.h>

#define VOCAB 50000
#define EMBD  256
#define HID   512
#define BSZ   64
#define SEQ   1024
#define NGRP  8
#define GSZ   16
#define NCTA  (NGRP*GSZ)
#define TPB   256

__device__ float g_P[VOCAB * HID];
__device__ float g_Hb[2][1024 * BSZ];
__device__ unsigned g_cnt[NGRP * 32];
__device__ unsigned g_gen[NGRP * 32];

typedef unsigned long long ull;

__device__ __forceinline__ ull pk2(float x, float y) {
    ull r; asm("mov.b64 %0,{%1,%2};" : "=l"(r) : "f"(x), "f"(y)); return r;
}
__device__ __forceinline__ void upk2(ull v, float& x, float& y) {
    asm("mov.b64 {%0,%1},%2;" : "=f"(x), "=f"(y) : "l"(v));
}
__device__ __forceinline__ void fma2(ull& d, ull a, ull b) {
    asm("fma.rn.f32x2 %0,%1,%2,%0;" : "+l"(d) : "l"(a), "l"(b));
}
__device__ __forceinline__ ull add2(ull a, ull b) {
    ull r; asm("add.rn.f32x2 %0,%1,%2;" : "=l"(r) : "l"(a), "l"(b)); return r;
}

__device__ __forceinline__ void group_barrier(int g) {
    __threadfence();
    __syncthreads();
    if (threadIdx.x == 0) {
        volatile unsigned* vgen = &g_gen[g * 32];
        unsigned gen = *vgen;
        if (atomicAdd(&g_cnt[g * 32], 1u) == GSZ - 1u) {
            atomicExch(&g_cnt[g * 32], 0u);
            __threadfence();
            *vgen = gen + 1u;
        } else {
            while (*vgen == gen) { }
        }
        __threadfence();
    }
    __syncthreads();
}

// ---------------- kernel 1: P = emb @ Wxh0 + bxh0 + bhh0 ----------------
__global__ __launch_bounds__(256) void proj_kernel(
    const float* __restrict__ emb, const float* __restrict__ Wxh0,
    const float* __restrict__ bxh0, const float* __restrict__ bhh0)
{
    __shared__ float As[16][136];
    __shared__ float Bs[16][136];
    const int tid = threadIdx.x;
    const int bm = blockIdx.y * 128, bn = blockIdx.x * 128;
    const int tx = tid & 15, ty = tid >> 4;

    ull acc2[8][4];
    #pragma unroll
    for (int i = 0; i < 8; ++i)
        #pragma unroll
        for (int j = 0; j < 4; ++j) acc2[i][j] = 0ULL;

    for (int k0 = 0; k0 < EMBD; k0 += 16) {
        #pragma unroll
        for (int q = 0; q < 2; ++q) {
            int idx = tid + q * 256;
            int m = idx >> 2, kq = (idx & 3) * 4, gm = bm + m;
            float4 e = make_float4(0.f, 0.f, 0.f, 0.f);
            if (gm < VOCAB) e = *reinterpret_cast<const float4*>(&emb[gm * EMBD + k0 + kq]);
            As[kq + 0][m] = e.x; As[kq + 1][m] = e.y; As[kq + 2][m] = e.z; As[kq + 3][m] = e.w;
        }
        #pragma unroll
        for (int q = 0; q < 2; ++q) {
            int idx = tid + q * 256;
            int kk = idx >> 5, j4 = (idx & 31) * 4;
            *reinterpret_cast<float4*>(&Bs[kk][j4]) =
                *reinterpret_cast<const float4*>(&Wxh0[(k0 + kk) * HID + bn + j4]);
        }
        __syncthreads();
        #pragma unroll
        for (int kk = 0; kk < 16; ++kk) {
            float4 a0 = *reinterpret_cast<const float4*>(&As[kk][ty * 8]);
            float4 a1 = *reinterpret_cast<const float4*>(&As[kk][ty * 8 + 4]);
            ulonglong2 b0 = *reinterpret_cast<const ulonglong2*>(&Bs[kk][tx * 8]);
            ulonglong2 b1 = *reinterpret_cast<const ulonglong2*>(&Bs[kk][tx * 8 + 4]);
            float am[8] = {a0.x, a0.y, a0.z, a0.w, a1.x, a1.y, a1.z, a1.w};
            ull bp[4] = {b0.x, b0.y, b1.x, b1.y};
            #pragma unroll
            for (int i = 0; i < 8; ++i) {
                ull ai = pk2(am[i], am[i]);
                #pragma unroll
                for (int j = 0; j < 4; ++j) fma2(acc2[i][j], ai, bp[j]);
            }
        }
        __syncthreads();
    }
    float bj[8];
    #pragma unroll
    for (int j = 0; j < 8; ++j) {
        int jg = bn + tx * 8 + j;
        bj[j] = __ldg(&bxh0[jg]) + __ldg(&bhh0[jg]);
    }
    #pragma unroll
    for (int i = 0; i < 8; ++i) {
        int gm = bm + ty * 8 + i;
        if (gm < VOCAB) {
            float o[8];
            #pragma unroll
            for (int j = 0; j < 4; ++j) upk2(acc2[i][j], o[2 * j], o[2 * j + 1]);
            float4 o0 = make_float4(o[0] + bj[0], o[1] + bj[1], o[2] + bj[2], o[3] + bj[3]);
            float4 o1 = make_float4(o[4] + bj[4], o[5] + bj[5], o[6] + bj[6], o[7] + bj[7]);
            *reinterpret_cast<float4*>(&g_P[gm * HID + bn + tx * 8])     = o0;
            *reinterpret_cast<float4*>(&g_P[gm * HID + bn + tx * 8 + 4]) = o1;
        }
    }
}

// ---------------- SMEM layout (floats) ----------------
#define SM_WA   0
#define SM_WB   16384
#define SM_HR   49152
#define SM_RED  (SM_HR + 4096)
#define SMEM_FLOATS (SM_HR + 8320)
#define RNN_SMEM (SMEM_FLOATS * (int)sizeof(float))   // 229888 B

__device__ __forceinline__ int swz1(int o) { return o ^ (((o >> 6) & 3) * 4); }

template<int KSLOG>
__device__ __forceinline__ void kstep(const float* __restrict__ W, const float* __restrict__ HRs,
                                      int k, int jl0, int bl0, ull acc[4][4])
{
    int wsw = ((k >> KSLOG) & 3) * 4;
    const float* wr = &W[k * 32];
    ulonglong2 wlo = *reinterpret_cast<const ulonglong2*>(&wr[(jl0)     ^ wsw]);
    ulonglong2 whi = *reinterpret_cast<const ulonglong2*>(&wr[(jl0 + 4) ^ wsw]);
    int hsw = ((k >> 4) & 1) * 4;
    float4 hv = *reinterpret_cast<const float4*>(&HRs[k * 8 + (bl0 ^ hsw)]);
    ull hb[4] = {pk2(hv.x, hv.x), pk2(hv.y, hv.y), pk2(hv.z, hv.z), pk2(hv.w, hv.w)};
    ull w4[4] = {wlo.x, wlo.y, whi.x, whi.y};
    #pragma unroll
    for (int a = 0; a < 4; ++a)
        #pragma unroll
        for (int b = 0; b < 4; ++b) fma2(acc[a][b], w4[a], hb[b]);
}

__device__ __forceinline__ void reduce_shfl(ull acc[4][4]) {
    #pragma unroll
    for (int a = 0; a < 4; ++a)
        #pragma unroll
        for (int b = 0; b < 4; ++b)
            acc[a][b] = add2(acc[a][b], __shfl_xor_sync(0xFFFFFFFFu, acc[a][b], 8));
}

__device__ __forceinline__ void stage1(float* __restrict__ RED, const ull acc[4][4],
                                       int kt, int jl0, int bl0)
{
    if ((kt & 1) == 0) {
        float* R = RED + (kt >> 1) * 264;
        #pragma unroll
        for (int a = 0; a < 4; ++a) {
            int j = jl0 + 2 * a;
            #pragma unroll
            for (int bb = 0; bb < 4; ++bb) {
                float lo, hi;
                upk2(acc[a][bb], lo, hi);
                int b = bl0 + bb;
                R[swz1(j * 8 + b)]       = lo;
                R[swz1((j + 1) * 8 + b)] = hi;
            }
        }
    }
}

__device__ __forceinline__ float stage2(const float* __restrict__ RED, int so) {
    float s = 0.f;
    #pragma unroll
    for (int q = 0; q < 16; ++q) s += RED[q * 264 + so];
    return s;
}

// ---------------- kernel 2: persistent RNN, 8 independent batch groups ----------------
__global__ __launch_bounds__(TPB, 1) void rnn_kernel(
    const int* __restrict__ x,
    const float* __restrict__ Whh0,
    const float* __restrict__ Wxh1, const float* __restrict__ Whh1,
    const float* __restrict__ bxh1, const float* __restrict__ bhh1,
    const float* __restrict__ fc_w, const float* __restrict__ fc_b,
    float* __restrict__ out)
{
    extern __shared__ float smem[];
    float* Wa  = smem + SM_WA;
    float* Wb  = smem + SM_WB;
    float* HRs = smem + SM_HR;
    float* RED = smem + SM_RED;

    const int tid  = threadIdx.x;
    const int g    = blockIdx.x >> 4;
    const int rank = blockIdx.x & 15;
    const int b0c  = g * 8;
    const int j0   = rank * 32;

    const int jt  = tid & 3;
    const int bt  = (tid >> 2) & 1;
    const int kt  = tid >> 3;        // 0..31
    const int jl0 = jt * 8;
    const int bl0 = bt * 4;
    const int oj  = tid >> 3;        // stage-2 output: local j 0..31
    const int ob  = tid & 7;         //                 local b 0..7
    const int so  = swz1(tid);

    // weights into SMEM once
    #pragma unroll
    for (int i = 0; i < 16; ++i) {
        int idx = tid + i * TPB;
        int k = idx >> 3, c4 = (idx & 7) << 2;
        float4 v = *reinterpret_cast<const float4*>(&Whh0[k * HID + j0 + c4]);
        int sw = ((k >> 4) & 3) * 4;
        *reinterpret_cast<float4*>(&Wa[k * 32 + (c4 ^ sw)]) = v;
    }
    #pragma unroll
    for (int i = 0; i < 32; ++i) {
        int idx = tid + i * TPB;
        int k = idx >> 3, c4 = (idx & 7) << 2;
        const float* src = (k < 512) ? &Wxh1[k * HID + j0 + c4]
                                     : &Whh1[(k - 512) * HID + j0 + c4];
        float4 v = *reinterpret_cast<const float4*>(src);
        int sw = ((k >> 5) & 3) * 4;
        *reinterpret_cast<float4*>(&Wb[k * 32 + (c4 ^ sw)]) = v;
    }

    const float biasB = __ldg(&bxh1[j0 + oj]) + __ldg(&bhh1[j0 + oj]);

    // zero this group's columns of both state buffers
    #pragma unroll
    for (int i = 0; i < 4; ++i) {
        int idx = rank * TPB + tid + i * 4096;   // 0..16383
        int q = idx >> 13, r = idx & 8191;
        g_Hb[q][(r >> 3) * 64 + b0c + (r & 7)] = 0.f;
    }
    group_barrier(g);

    for (int p = 0; p <= SEQ; ++p) {
        int pp = (p < SEQ) ? p : 0;
        int tok = __ldg(&x[(b0c + ob) * SEQ + pp]);
        float pP = __ldg(&g_P[tok * HID + j0 + oj]);

        const float* Hc = &g_Hb[p & 1][0];
        float*       Hn = &g_Hb[(p & 1) ^ 1][0];

        // stage state [1024 k][8 b] into SMEM via L2 (L1 stale across barrier)
        #pragma unroll
        for (int i = 0; i < 8; ++i) {
            int idx = tid + i * TPB;             // 0..2047
            int k = idx >> 1, c4 = (idx & 1) << 2;
            float4 v = __ldcg(reinterpret_cast<const float4*>(&Hc[k * 64 + b0c + c4]));
            int hsw = ((k >> 4) & 1) * 4;
            *reinterpret_cast<float4*>(&HRs[k * 8 + (c4 ^ hsw)]) = v;
        }
        __syncthreads();

        // job B: h1(p-1) = tanh([h0(p-1);h1(p-2)] @ Wb + bias)
        {
            ull acc[4][4];
            #pragma unroll
            for (int a = 0; a < 4; ++a)
                #pragma unroll
                for (int b = 0; b < 4; ++b) acc[a][b] = 0ULL;
            int ks = kt * 32;
            #pragma unroll
            for (int kk = 0; kk < 32; ++kk) kstep<5>(Wb, HRs, ks + kk, jl0, bl0, acc);
            reduce_shfl(acc);
            __syncthreads();                  // all HRs reads done before RED overlay
            stage1(RED, acc, kt, jl0, bl0);
        }
        __syncthreads();
        {
            float s = stage2(RED, so);
            if (p >= 1)
                Hn[(512 + j0 + oj) * 64 + b0c + ob] = tanhf(s + biasB);
        }

        // job A: h0(p) = tanh(P[x[b,p]] + h0(p-1) @ Wa)   (reads HRs rows < 512 only)
        {
            ull acc[4][4];
            #pragma unroll
            for (int a = 0; a < 4; ++a)
                #pragma unroll
                for (int b = 0; b < 4; ++b) acc[a][b] = 0ULL;
            int ks = kt * 16;
            #pragma unroll
            for (int kk = 0; kk < 16; ++kk) kstep<4>(Wa, HRs, ks + kk, jl0, bl0, acc);
            reduce_shfl(acc);
            __syncthreads();                  // B stage-2 RED reads done
            stage1(RED, acc, kt, jl0, bl0);
        }
        __syncthreads();
        {
            float s = stage2(RED, so);
            if (p < SEQ)
                Hn[(j0 + oj) * 64 + b0c + ob] = tanhf(s + pP);
        }

        group_barrier(g);
    }

    // final FC: out[b] = sigmoid(h1(SEQ-1) . fc_w + fc_b); h1 in g_Hb[1] rows 512+
    if (rank == 0) {
        int b = tid >> 5, l = tid & 31;
        float s = 0.f;
        #pragma unroll
        for (int i = 0; i < 16; ++i) {
            int k = l + i * 32;
            s += __ldcg(&g_Hb[1][(512 + k) * 64 + b0c + b]) * __ldg(&fc_w[k]);
        }
        #pragma unroll
        for (int off = 16; off; off >>= 1)
            s += __shfl_xor_sync(0xFFFFFFFFu, s, off);
        if (l == 0)
            out[b0c + b] = 1.f / (1.f + expf(-(s + __ldg(&fc_b[0]))));
    }
}

extern "C" void kernel_launch(void* const* d_in, const int* in_sizes, int n_in,
                              void* d_out, int out_size)
{
    const int*   x    = (const int*)  d_in[0];
    const float* emb  = (const float*)d_in[1];
    const float* Wxh0 = (const float*)d_in[2];
    const float* bxh0 = (const float*)d_in[3];
    const float* Whh0 = (const float*)d_in[4];
    const float* bhh0 = (const float*)d_in[5];
    const float* Wxh1 = (const float*)d_in[6];
    const float* bxh1 = (const float*)d_in[7];
    const float* Whh1 = (const float*)d_in[8];
    const float* bhh1 = (const float*)d_in[9];
    const float* fc_w = (const float*)d_in[10];
    const float* fc_b = (const float*)d_in[11];
    float* out = (float*)d_out;

    cudaFuncSetAttribute(rnn_kernel, cudaFuncAttributeMaxDynamicSharedMemorySize, RNN_SMEM);

    dim3 gp(HID / 128, (VOCAB + 127) / 128);
    proj_kernel<<<gp, 256>>>(emb, Wxh0, bxh0, bhh0);
    rnn_kernel<<<NCTA, TPB, RNN_SMEM>>>(x, Whh0, Wxh1, Whh1, bxh1, bhh1, fc_w, fc_b, out);
}

// round 16
// speedup vs baseline: 1.2787x; 1.1572x over previous
#include <cuda_runtime.h>
#include <math.h>

#define VOCAB 50000
#define EMBD  256
#define HID   512
#define BSZ   64
#define SEQ   1024
#define NGRP  8
#define GSZ   16
#define NCTA  (NGRP*GSZ)
#define TPB   256

// ---------------- device-global scratch (no allocation APIs) ----------------
__device__ float g_P[VOCAB * HID];       // projected embedding + layer0 biases
__device__ float g_Hb[2][1024 * BSZ];    // double-buffered [h0(512); h1(512)] x [64 b]
__device__ unsigned g_flag[NCTA * 32];   // per-CTA monotonic phase flags (padded)

typedef unsigned long long ull;

__device__ __forceinline__ ull pk2(float x, float y) {
    ull r; asm("mov.b64 %0,{%1,%2};" : "=l"(r) : "f"(x), "f"(y)); return r;
}
__device__ __forceinline__ void upk2(ull v, float& x, float& y) {
    asm("mov.b64 {%0,%1},%2;" : "=f"(x), "=f"(y) : "l"(v));
}
__device__ __forceinline__ void fma2(ull& d, ull a, ull b) {
    asm("fma.rn.f32x2 %0,%1,%2,%0;" : "+l"(d) : "l"(a), "l"(b));
}
__device__ __forceinline__ unsigned ld_acq(const unsigned* p) {
    unsigned v; asm volatile("ld.acquire.gpu.u32 %0,[%1];" : "=r"(v) : "l"(p) : "memory");
    return v;
}
// k-column swizzle (same for W and H smem; preserves 16B alignment for k%4==0)
__device__ __forceinline__ int swzc(int k) {
    return k ^ ((((k >> 5) ^ (k >> 8)) & 7) << 2);
}

// ---------------- kernel 1: P = emb @ Wxh0 + bxh0 + bhh0 ----------------
__global__ __launch_bounds__(256) void proj_kernel(
    const float* __restrict__ emb, const float* __restrict__ Wxh0,
    const float* __restrict__ bxh0, const float* __restrict__ bhh0)
{
    __shared__ float As[16][136];
    __shared__ float Bs[16][136];
    const int tid = threadIdx.x;
    const int bm = blockIdx.y * 128, bn = blockIdx.x * 128;
    const int tx = tid & 15, ty = tid >> 4;

    ull acc2[8][4];
    #pragma unroll
    for (int i = 0; i < 8; ++i)
        #pragma unroll
        for (int j = 0; j < 4; ++j) acc2[i][j] = 0ULL;

    for (int k0 = 0; k0 < EMBD; k0 += 16) {
        #pragma unroll
        for (int q = 0; q < 2; ++q) {
            int idx = tid + q * 256;
            int m = idx >> 2, kq = (idx & 3) * 4, gm = bm + m;
            float4 e = make_float4(0.f, 0.f, 0.f, 0.f);
            if (gm < VOCAB) e = *reinterpret_cast<const float4*>(&emb[gm * EMBD + k0 + kq]);
            As[kq + 0][m] = e.x; As[kq + 1][m] = e.y; As[kq + 2][m] = e.z; As[kq + 3][m] = e.w;
        }
        #pragma unroll
        for (int q = 0; q < 2; ++q) {
            int idx = tid + q * 256;
            int kk = idx >> 5, j4 = (idx & 31) * 4;
            *reinterpret_cast<float4*>(&Bs[kk][j4]) =
                *reinterpret_cast<const float4*>(&Wxh0[(k0 + kk) * HID + bn + j4]);
        }
        __syncthreads();
        #pragma unroll
        for (int kk = 0; kk < 16; ++kk) {
            float4 a0 = *reinterpret_cast<const float4*>(&As[kk][ty * 8]);
            float4 a1 = *reinterpret_cast<const float4*>(&As[kk][ty * 8 + 4]);
            ulonglong2 b0 = *reinterpret_cast<const ulonglong2*>(&Bs[kk][tx * 8]);
            ulonglong2 b1 = *reinterpret_cast<const ulonglong2*>(&Bs[kk][tx * 8 + 4]);
            float am[8] = {a0.x, a0.y, a0.z, a0.w, a1.x, a1.y, a1.z, a1.w};
            ull bp[4] = {b0.x, b0.y, b1.x, b1.y};
            #pragma unroll
            for (int i = 0; i < 8; ++i) {
                ull ai = pk2(am[i], am[i]);
                #pragma unroll
                for (int j = 0; j < 4; ++j) fma2(acc2[i][j], ai, bp[j]);
            }
        }
        __syncthreads();
    }
    float bj[8];
    #pragma unroll
    for (int j = 0; j < 8; ++j) {
        int jg = bn + tx * 8 + j;
        bj[j] = __ldg(&bxh0[jg]) + __ldg(&bhh0[jg]);
    }
    #pragma unroll
    for (int i = 0; i < 8; ++i) {
        int gm = bm + ty * 8 + i;
        if (gm < VOCAB) {
            float o[8];
            #pragma unroll
            for (int j = 0; j < 4; ++j) upk2(acc2[i][j], o[2 * j], o[2 * j + 1]);
            float4 o0 = make_float4(o[0] + bj[0], o[1] + bj[1], o[2] + bj[2], o[3] + bj[3]);
            float4 o1 = make_float4(o[4] + bj[4], o[5] + bj[5], o[6] + bj[6], o[7] + bj[7]);
            *reinterpret_cast<float4*>(&g_P[gm * HID + bn + tx * 8])     = o0;
            *reinterpret_cast<float4*>(&g_P[gm * HID + bn + tx * 8 + 4]) = o1;
        }
    }
}

// ---------------- RNN building blocks ----------------
// per-4k step: k-pair f32x2 FMAs, W[j][k] k-major, H[b][k] k-major
template<int KSTRIDE>
__device__ __forceinline__ void kstep4(const float* __restrict__ W,
                                       const float* __restrict__ H,
                                       int k, int jb, int bb, ull acc[4][4])
{
    int c = swzc(k);
    ulonglong2 wv[4], hv[4];
    #pragma unroll
    for (int a = 0; a < 4; ++a)
        wv[a] = *reinterpret_cast<const ulonglong2*>(&W[(jb + a) * KSTRIDE + c]);
    #pragma unroll
    for (int u = 0; u < 4; ++u)
        hv[u] = *reinterpret_cast<const ulonglong2*>(&H[(bb + u) * 1032 + c]);
    #pragma unroll
    for (int a = 0; a < 4; ++a)
        #pragma unroll
        for (int u = 0; u < 4; ++u) {
            fma2(acc[a][u], wv[a].x, hv[u].x);
            fma2(acc[a][u], wv[a].y, hv[u].y);
        }
}

// in-warp tree reduction over 16 k-slices (lane bits 0-3); lane ends owning
// output index (lane&15): a=(lane>>2)&3 (j), c=lane&3 (b)
__device__ __forceinline__ float treereduce(ull acc[4][4], int lane) {
    float f[16];
    #pragma unroll
    for (int a = 0; a < 4; ++a)
        #pragma unroll
        for (int c = 0; c < 4; ++c) {
            float lo, hi; upk2(acc[a][c], lo, hi);
            f[a * 4 + c] = lo + hi;
        }
    #pragma unroll
    for (int s = 8; s >= 1; s >>= 1) {
        bool up = (lane & s) != 0;
        #pragma unroll
        for (int i = 0; i < s; ++i) {
            float x = f[i], y = f[i + s];
            float ox = __shfl_xor_sync(0xFFFFFFFFu, x, s);
            float oy = __shfl_xor_sync(0xFFFFFFFFu, y, s);
            f[i] = up ? (y + oy) : (x + ox);
        }
    }
    return f[0];
}

// SMEM: Wa[32j][512k] 16384 | Wb[32j][1024k] 32768 | HRs[8b][1032] 8256
#define SM_WB 16384
#define SM_HR 49152
#define SMEM_FLOATS (SM_HR + 8 * 1032)
#define RNN_SMEM (SMEM_FLOATS * (int)sizeof(float))   // 229632 B

// ---------------- kernel 2: persistent RNN, flag-synced groups ----------------
__global__ __launch_bounds__(TPB, 1) void rnn_kernel(
    const int* __restrict__ x,
    const float* __restrict__ Whh0,
    const float* __restrict__ Wxh1, const float* __restrict__ Whh1,
    const float* __restrict__ bxh1, const float* __restrict__ bhh1,
    const float* __restrict__ fc_w, const float* __restrict__ fc_b,
    float* __restrict__ out)
{
    extern __shared__ float smem[];
    float* Wa  = smem;
    float* Wb  = smem + SM_WB;
    float* HRs = smem + SM_HR;

    const int tid  = threadIdx.x;
    const int cid  = blockIdx.x;
    const int g    = cid >> 4;
    const int rank = cid & 15;
    const int b0c  = g * 8;
    const int j0   = rank * 32;

    const int lane = tid & 31;
    const int warp = tid >> 5;
    const int kt   = lane & 15;
    const int bh   = (lane >> 4) & 1;
    const int jb   = warp * 4;             // local j base (compute tile)
    const int bb   = bh * 4;               // local b base
    const int jOut = j0 + jb + ((lane >> 2) & 3);   // this lane's output j (global row)
    const int bOutL = bb + (lane & 3);              // local b
    const int bOut  = b0c + bOutL;                  // global batch

    const unsigned base = *(volatile unsigned*)&g_flag[cid * 32];

    // ---- weights into SMEM once: transposed to [j][k], k-swizzled ----
    #pragma unroll
    for (int i = 0; i < 16; ++i) {
        int lin = tid + i * TPB;           // 0..4095
        int k = lin >> 3, j4 = (lin & 7) << 2;
        float4 v = *reinterpret_cast<const float4*>(&Whh0[k * HID + j0 + j4]);
        int c = swzc(k);
        Wa[(j4 + 0) * 512 + c] = v.x; Wa[(j4 + 1) * 512 + c] = v.y;
        Wa[(j4 + 2) * 512 + c] = v.z; Wa[(j4 + 3) * 512 + c] = v.w;
    }
    #pragma unroll
    for (int i = 0; i < 32; ++i) {
        int lin = tid + i * TPB;           // 0..8191
        int k = lin >> 3, j4 = (lin & 7) << 2;
        const float* src = (k < 512) ? &Wxh1[k * HID + j0 + j4]
                                     : &Whh1[(k - 512) * HID + j0 + j4];
        float4 v = *reinterpret_cast<const float4*>(src);
        int c = swzc(k);
        Wb[(j4 + 0) * 1024 + c] = v.x; Wb[(j4 + 1) * 1024 + c] = v.y;
        Wb[(j4 + 2) * 1024 + c] = v.z; Wb[(j4 + 3) * 1024 + c] = v.w;
    }
    const float biasB = __ldg(&bxh1[jOut]) + __ldg(&bhh1[jOut]);

    const int peer = tid >> 4, q = tid & 15;        // staging: 16 threads per peer
    const unsigned* peerFlag = &g_flag[((g << 4) | peer) * 32];

    for (int p = 0; p <= SEQ; ++p) {
        // prefetch token + projected embedding (off the critical path)
        int pp = (p < SEQ) ? p : 0;
        int tok = __ldg(&x[bOut * SEQ + pp]);
        float pP = __ldg(&g_P[tok * HID + jOut]);

        const float* Hc = &g_Hb[p & 1][0];
        float*       Hn = &g_Hb[(p & 1) ^ 1][0];

        if (p == 0) {
            #pragma unroll
            for (int i = 0; i < 33; ++i) {
                int idx = tid + i * TPB;
                if (idx < 8 * 1032) HRs[idx] = 0.f;
            }
        } else {
            unsigned want = base + (unsigned)p;
            while (ld_acq(peerFlag) < want) { }
            // stage peer's 64 rows (32 h0 + 32 h1), transpose to [b][k]
            #pragma unroll
            for (int i = 0; i < 8; ++i) {
                int f = q + (i << 4);             // 0..127
                int half = f >> 6;
                int r = (f >> 1) & 31;
                int row = half * 512 + peer * 32 + r;
                int c4 = (f & 1) << 2;
                float4 v = __ldcg(reinterpret_cast<const float4*>(&Hc[row * 64 + b0c + c4]));
                int c = swzc(row);
                HRs[(c4 + 0) * 1032 + c] = v.x;
                HRs[(c4 + 1) * 1032 + c] = v.y;
                HRs[(c4 + 2) * 1032 + c] = v.z;
                HRs[(c4 + 3) * 1032 + c] = v.w;
            }
        }
        __syncthreads();

        // ---- job B: h1(p-1) = tanh([h0(p-1);h1(p-2)] @ Wb + bias) ----
        {
            ull acc[4][4];
            #pragma unroll
            for (int a = 0; a < 4; ++a)
                #pragma unroll
                for (int u = 0; u < 4; ++u) acc[a][u] = 0ULL;
            int ks = kt * 64;
            #pragma unroll 4
            for (int kk = 0; kk < 16; ++kk)
                kstep4<1024>(Wb, HRs, ks + (kk << 2), jb, bb, acc);
            float s = treereduce(acc, lane);
            float val = (p >= 1) ? tanhf(s + biasB) : 0.f;   // h1(-1) = 0
            Hn[(512 + jOut) * 64 + bOut] = val;
        }

        // ---- job A: h0(p) = tanh(P[x[b,p]] + h0(p-1) @ Wa) ----
        {
            ull acc[4][4];
            #pragma unroll
            for (int a = 0; a < 4; ++a)
                #pragma unroll
                for (int u = 0; u < 4; ++u) acc[a][u] = 0ULL;
            int ks = kt * 32;
            #pragma unroll 4
            for (int kk = 0; kk < 8; ++kk)
                kstep4<512>(Wa, HRs, ks + (kk << 2), jb, bb, acc);
            float s = treereduce(acc, lane);
            if (p < SEQ)
                Hn[jOut * 64 + bOut] = tanhf(s + pP);
        }

        __threadfence();          // release all this CTA's stores (every thread)
        __syncthreads();
        if (tid == 0)
            *(volatile unsigned*)&g_flag[cid * 32] = base + (unsigned)p + 1u;
    }

    // ---- final FC: out[b] = sigmoid(h1(SEQ-1) . fc_w + fc_b); h1 in g_Hb[1] rows 512+ ----
    if (rank == 0) {
        if (tid < GSZ) {
            unsigned want = base + (unsigned)(SEQ + 1);
            while (ld_acq(&g_flag[((g << 4) | tid) * 32]) < want) { }
        }
        __syncthreads();
        int b = tid >> 5, l = tid & 31;
        float s = 0.f;
        #pragma unroll
        for (int i = 0; i < 16; ++i) {
            int k = l + i * 32;
            s += __ldcg(&g_Hb[1][(512 + k) * 64 + b0c + b]) * __ldg(&fc_w[k]);
        }
        #pragma unroll
        for (int off = 16; off; off >>= 1)
            s += __shfl_xor_sync(0xFFFFFFFFu, s, off);
        if (l == 0)
            out[b0c + b] = 1.f / (1.f + expf(-(s + __ldg(&fc_b[0]))));
    }
}

extern "C" void kernel_launch(void* const* d_in, const int* in_sizes, int n_in,
                              void* d_out, int out_size)
{
    const int*   x    = (const int*)  d_in[0];
    const float* emb  = (const float*)d_in[1];
    const float* Wxh0 = (const float*)d_in[2];
    const float* bxh0 = (const float*)d_in[3];
    const float* Whh0 = (const float*)d_in[4];
    const float* bhh0 = (const float*)d_in[5];
    const float* Wxh1 = (const float*)d_in[6];
    const float* bxh1 = (const float*)d_in[7];
    const float* Whh1 = (const float*)d_in[8];
    const float* bhh1 = (const float*)d_in[9];
    const float* fc_w = (const float*)d_in[10];
    const float* fc_b = (const float*)d_in[11];
    float* out = (float*)d_out;

    cudaFuncSetAttribute(rnn_kernel, cudaFuncAttributeMaxDynamicSharedMemorySize, RNN_SMEM);

    dim3 gp(HID / 128, (VOCAB + 127) / 128);
    proj_kernel<<<gp, 256>>>(emb, Wxh0, bxh0, bhh0);
    rnn_kernel<<<NCTA, TPB, RNN_SMEM>>>(x, Whh0, Wxh1, Whh1, bxh1, bhh1, fc_w, fc_b, out);
}

// round 17
// speedup vs baseline: 1.3307x; 1.0406x over previous
#include <cuda_runtime.h>
#include <math.h>

#define VOCAB 50000
#define EMBD  256
#define HID   512
#define BSZ   64
#define SEQ   1024
#define NGRP  8
#define GSZ   16
#define NCTA  (NGRP*GSZ)
#define TPB   256

// ---------------- device-global scratch (no allocation APIs) ----------------
__device__ float g_P[VOCAB * HID];       // projected embedding + layer0 biases
__device__ float g_Hb[2][BSZ * 1024];    // double-buffered, [b][k]: h0 = [b][j], h1 = [b][512+j]
__device__ unsigned g_flag[NCTA * 32];   // per-CTA monotonic phase flags (padded)

typedef unsigned long long ull;

__device__ __forceinline__ ull pk2(float x, float y) {
    ull r; asm("mov.b64 %0,{%1,%2};" : "=l"(r) : "f"(x), "f"(y)); return r;
}
__device__ __forceinline__ void upk2(ull v, float& x, float& y) {
    asm("mov.b64 {%0,%1},%2;" : "=f"(x), "=f"(y) : "l"(v));
}
__device__ __forceinline__ void fma2(ull& d, ull a, ull b) {
    asm("fma.rn.f32x2 %0,%1,%2,%0;" : "+l"(d) : "l"(a), "l"(b));
}
__device__ __forceinline__ unsigned ld_acq(const unsigned* p) {
    unsigned v; asm volatile("ld.acquire.gpu.u32 %0,[%1];" : "=r"(v) : "l"(p) : "memory");
    return v;
}
__device__ __forceinline__ void st_rel(unsigned* p, unsigned v) {
    asm volatile("st.release.gpu.u32 [%0],%1;" :: "l"(p), "r"(v) : "memory");
}
// k-column swizzle; preserves 16B alignment (xors bits >= 2 of float index)
__device__ __forceinline__ int swzc(int k) {
    return k ^ ((((k >> 5) ^ (k >> 8)) & 7) << 2);
}

// ---------------- kernel 1: P = emb @ Wxh0 + bxh0 + bhh0 ----------------
__global__ __launch_bounds__(256) void proj_kernel(
    const float* __restrict__ emb, const float* __restrict__ Wxh0,
    const float* __restrict__ bxh0, const float* __restrict__ bhh0)
{
    __shared__ float As[16][136];
    __shared__ float Bs[16][136];
    const int tid = threadIdx.x;
    const int bm = blockIdx.y * 128, bn = blockIdx.x * 128;
    const int tx = tid & 15, ty = tid >> 4;

    ull acc2[8][4];
    #pragma unroll
    for (int i = 0; i < 8; ++i)
        #pragma unroll
        for (int j = 0; j < 4; ++j) acc2[i][j] = 0ULL;

    for (int k0 = 0; k0 < EMBD; k0 += 16) {
        #pragma unroll
        for (int q = 0; q < 2; ++q) {
            int idx = tid + q * 256;
            int m = idx >> 2, kq = (idx & 3) * 4, gm = bm + m;
            float4 e = make_float4(0.f, 0.f, 0.f, 0.f);
            if (gm < VOCAB) e = *reinterpret_cast<const float4*>(&emb[gm * EMBD + k0 + kq]);
            As[kq + 0][m] = e.x; As[kq + 1][m] = e.y; As[kq + 2][m] = e.z; As[kq + 3][m] = e.w;
        }
        #pragma unroll
        for (int q = 0; q < 2; ++q) {
            int idx = tid + q * 256;
            int kk = idx >> 5, j4 = (idx & 31) * 4;
            *reinterpret_cast<float4*>(&Bs[kk][j4]) =
                *reinterpret_cast<const float4*>(&Wxh0[(k0 + kk) * HID + bn + j4]);
        }
        __syncthreads();
        #pragma unroll
        for (int kk = 0; kk < 16; ++kk) {
            float4 a0 = *reinterpret_cast<const float4*>(&As[kk][ty * 8]);
            float4 a1 = *reinterpret_cast<const float4*>(&As[kk][ty * 8 + 4]);
            ulonglong2 b0 = *reinterpret_cast<const ulonglong2*>(&Bs[kk][tx * 8]);
            ulonglong2 b1 = *reinterpret_cast<const ulonglong2*>(&Bs[kk][tx * 8 + 4]);
            float am[8] = {a0.x, a0.y, a0.z, a0.w, a1.x, a1.y, a1.z, a1.w};
            ull bp[4] = {b0.x, b0.y, b1.x, b1.y};
            #pragma unroll
            for (int i = 0; i < 8; ++i) {
                ull ai = pk2(am[i], am[i]);
                #pragma unroll
                for (int j = 0; j < 4; ++j) fma2(acc2[i][j], ai, bp[j]);
            }
        }
        __syncthreads();
    }
    float bj[8];
    #pragma unroll
    for (int j = 0; j < 8; ++j) {
        int jg = bn + tx * 8 + j;
        bj[j] = __ldg(&bxh0[jg]) + __ldg(&bhh0[jg]);
    }
    #pragma unroll
    for (int i = 0; i < 8; ++i) {
        int gm = bm + ty * 8 + i;
        if (gm < VOCAB) {
            float o[8];
            #pragma unroll
            for (int j = 0; j < 4; ++j) upk2(acc2[i][j], o[2 * j], o[2 * j + 1]);
            float4 o0 = make_float4(o[0] + bj[0], o[1] + bj[1], o[2] + bj[2], o[3] + bj[3]);
            float4 o1 = make_float4(o[4] + bj[4], o[5] + bj[5], o[6] + bj[6], o[7] + bj[7]);
            *reinterpret_cast<float4*>(&g_P[gm * HID + bn + tx * 8])     = o0;
            *reinterpret_cast<float4*>(&g_P[gm * HID + bn + tx * 8 + 4]) = o1;
        }
    }
}

// ---------------- RNN building blocks ----------------
// per-4k step: W[j][k] k-major, H[b][k] k-major, thread tile 4j x 8b
template<int KSTRIDE>
__device__ __forceinline__ void kstep4(const float* __restrict__ W,
                                       const float* __restrict__ H,
                                       int k, int jb, ull acc[4][8])
{
    int c = swzc(k);
    ulonglong2 wv[4], hv[8];
    #pragma unroll
    for (int a = 0; a < 4; ++a)
        wv[a] = *reinterpret_cast<const ulonglong2*>(&W[(jb + a) * KSTRIDE + c]);
    #pragma unroll
    for (int u = 0; u < 8; ++u)
        hv[u] = *reinterpret_cast<const ulonglong2*>(&H[u * 1032 + c]);
    #pragma unroll
    for (int a = 0; a < 4; ++a)
        #pragma unroll
        for (int u = 0; u < 8; ++u) {
            fma2(acc[a][u], wv[a].x, hv[u].x);
            fma2(acc[a][u], wv[a].y, hv[u].y);
        }
}

// butterfly reduction across 32 lanes x 32 elements; lane L ends owning element L
__device__ __forceinline__ float treereduce32(ull acc[4][8], int lane) {
    float f[32];
    #pragma unroll
    for (int a = 0; a < 4; ++a)
        #pragma unroll
        for (int c = 0; c < 8; ++c) {
            float lo, hi; upk2(acc[a][c], lo, hi);
            f[a * 8 + c] = lo + hi;
        }
    #pragma unroll
    for (int s = 16; s >= 1; s >>= 1) {
        bool up = (lane & s) != 0;
        #pragma unroll
        for (int i = 0; i < s; ++i) {
            float x = f[i], y = f[i + s];
            float ox = __shfl_xor_sync(0xFFFFFFFFu, x, s);
            float oy = __shfl_xor_sync(0xFFFFFFFFu, y, s);
            f[i] = up ? (y + oy) : (x + ox);
        }
    }
    return f[0];
}

// SMEM: Wa[32j][512k] 16384 | Wb[32j][1024k] 32768 | HRs[8b][1032] 8256
#define SM_WB 16384
#define SM_HR 49152
#define SMEM_FLOATS (SM_HR + 8 * 1032)
#define RNN_SMEM (SMEM_FLOATS * (int)sizeof(float))   // 229632 B

// ---------------- kernel 2: persistent RNN, flag-synced groups ----------------
__global__ __launch_bounds__(TPB, 1) void rnn_kernel(
    const int* __restrict__ x,
    const float* __restrict__ Whh0,
    const float* __restrict__ Wxh1, const float* __restrict__ Whh1,
    const float* __restrict__ bxh1, const float* __restrict__ bhh1,
    const float* __restrict__ fc_w, const float* __restrict__ fc_b,
    float* __restrict__ out)
{
    extern __shared__ float smem[];
    float* Wa  = smem;
    float* Wb  = smem + SM_WB;
    float* HRs = smem + SM_HR;

    const int tid  = threadIdx.x;
    const int cid  = blockIdx.x;
    const int g    = cid >> 4;
    const int rank = cid & 15;
    const int b0c  = g * 8;
    const int j0   = rank * 32;

    const int lane = tid & 31;
    const int warp = tid >> 5;
    const int jb   = warp * 4;                     // local j base of this warp's tile
    const int jOut = j0 + jb + (lane >> 3);        // lane's output j (global col of W)
    const int bOut = b0c + (lane & 7);             // lane's output batch

    const unsigned base = *(volatile unsigned*)&g_flag[cid * 32];

    // ---- weights into SMEM once: [j][k] k-major, k-swizzled ----
    #pragma unroll
    for (int i = 0; i < 16; ++i) {
        int lin = tid + i * TPB;           // 0..4095
        int k = lin >> 3, j4 = (lin & 7) << 2;
        float4 v = *reinterpret_cast<const float4*>(&Whh0[k * HID + j0 + j4]);
        int c = swzc(k);
        Wa[(j4 + 0) * 512 + c] = v.x; Wa[(j4 + 1) * 512 + c] = v.y;
        Wa[(j4 + 2) * 512 + c] = v.z; Wa[(j4 + 3) * 512 + c] = v.w;
    }
    #pragma unroll
    for (int i = 0; i < 32; ++i) {
        int lin = tid + i * TPB;           // 0..8191
        int k = lin >> 3, j4 = (lin & 7) << 2;
        const float* src = (k < 512) ? &Wxh1[k * HID + j0 + j4]
                                     : &Whh1[(k - 512) * HID + j0 + j4];
        float4 v = *reinterpret_cast<const float4*>(src);
        int c = swzc(k);
        Wb[(j4 + 0) * 1024 + c] = v.x; Wb[(j4 + 1) * 1024 + c] = v.y;
        Wb[(j4 + 2) * 1024 + c] = v.z; Wb[(j4 + 3) * 1024 + c] = v.w;
    }
    const float biasB = __ldg(&bxh1[jOut]) + __ldg(&bhh1[jOut]);

    // staging: 16 threads per peer CTA; peer P owns k in [P*32,P*32+32) of each half
    const int peer = tid >> 4, q = tid & 15;
    const unsigned* peerFlag = &g_flag[((g << 4) | peer) * 32];

    for (int p = 0; p <= SEQ; ++p) {
        // prefetch token + projected embedding (off the critical path)
        int pp = (p < SEQ) ? p : 0;
        int tok = __ldg(&x[bOut * SEQ + pp]);
        float pP = __ldg(&g_P[tok * HID + jOut]);

        const float* Hc = &g_Hb[p & 1][0];
        float*       Hn = &g_Hb[(p & 1) ^ 1][0];

        if (p == 0) {
            #pragma unroll
            for (int i = 0; i < 33; ++i) {
                int idx = tid + i * TPB;
                if (idx < 8 * 1032) HRs[idx] = 0.f;
            }
        } else {
            unsigned want = base + (unsigned)p;
            while (ld_acq(peerFlag) < want) { }
            // peer's slice: 8 b x 64 k (32 h0 + 32 h1), straight float4 copy
            #pragma unroll
            for (int i = 0; i < 8; ++i) {
                int f = q + (i << 4);                 // 0..127
                int b = f & 7;
                int t = f >> 3;                       // 0..15
                int k = (t >> 3) * 512 + peer * 32 + (t & 7) * 4;
                float4 v = __ldcg(reinterpret_cast<const float4*>(
                    &Hc[(b0c + b) * 1024 + k]));
                *reinterpret_cast<float4*>(&HRs[b * 1032 + swzc(k)]) = v;
            }
        }
        __syncthreads();

        // ---- job B: h1(p-1) = tanh([h0(p-1);h1(p-2)] @ Wb + bias) ----
        {
            ull acc[4][8];
            #pragma unroll
            for (int a = 0; a < 4; ++a)
                #pragma unroll
                for (int u = 0; u < 8; ++u) acc[a][u] = 0ULL;
            int ks = lane * 32;
            #pragma unroll 2
            for (int kk = 0; kk < 8; ++kk)
                kstep4<1024>(Wb, HRs, ks + (kk << 2), jb, acc);
            float s = treereduce32(acc, lane);
            float val = (p >= 1) ? tanhf(s + biasB) : 0.f;   // h1(-1) = 0
            Hn[bOut * 1024 + 512 + jOut] = val;
        }

        // ---- job A: h0(p) = tanh(P[x[b,p]] + h0(p-1) @ Wa) ----
        {
            ull acc[4][8];
            #pragma unroll
            for (int a = 0; a < 4; ++a)
                #pragma unroll
                for (int u = 0; u < 8; ++u) acc[a][u] = 0ULL;
            int ks = lane * 16;
            #pragma unroll 2
            for (int kk = 0; kk < 4; ++kk)
                kstep4<512>(Wa, HRs, ks + (kk << 2), jb, acc);
            float s = treereduce32(acc, lane);
            if (p < SEQ)
                Hn[bOut * 1024 + jOut] = tanhf(s + pP);
        }

        __syncthreads();                    // all stores issued before publish
        if (tid == 0)
            st_rel(&g_flag[cid * 32], base + (unsigned)p + 1u);
    }

    // ---- final FC: out[b] = sigmoid(h1(SEQ-1) . fc_w + fc_b); h1 in g_Hb[1][b][512+] ----
    if (rank == 0) {
        if (tid < GSZ) {
            unsigned want = base + (unsigned)(SEQ + 1);
            while (ld_acq(&g_flag[((g << 4) | tid) * 32]) < want) { }
        }
        __syncthreads();
        int b = tid >> 5, l = tid & 31;
        float s = 0.f;
        #pragma unroll
        for (int i = 0; i < 16; ++i) {
            int k = l + i * 32;
            s += __ldcg(&g_Hb[1][(b0c + b) * 1024 + 512 + k]) * __ldg(&fc_w[k]);
        }
        #pragma unroll
        for (int off = 16; off; off >>= 1)
            s += __shfl_xor_sync(0xFFFFFFFFu, s, off);
        if (l == 0)
            out[b0c + b] = 1.f / (1.f + expf(-(s + __ldg(&fc_b[0]))));
    }
}

extern "C" void kernel_launch(void* const* d_in, const int* in_sizes, int n_in,
                              void* d_out, int out_size)
{
    const int*   x    = (const int*)  d_in[0];
    const float* emb  = (const float*)d_in[1];
    const float* Wxh0 = (const float*)d_in[2];
    const float* bxh0 = (const float*)d_in[3];
    const float* Whh0 = (const float*)d_in[4];
    const float* bhh0 = (const float*)d_in[5];
    const float* Wxh1 = (const float*)d_in[6];
    const float* bxh1 = (const float*)d_in[7];
    const float* Whh1 = (const float*)d_in[8];
    const float* bhh1 = (const float*)d_in[9];
    const float* fc_w = (const float*)d_in[10];
    const float* fc_b = (const float*)d_in[11];
    float* out = (float*)d_out;

    cudaFuncSetAttribute(rnn_kernel, cudaFuncAttributeMaxDynamicSharedMemorySize, RNN_SMEM);

    dim3 gp(HID / 128, (VOCAB + 127) / 128);
    proj_kernel<<<gp, 256>>>(emb, Wxh0, bxh0, bhh0);
    rnn_kernel<<<NCTA, TPB, RNN_SMEM>>>(x, Whh0, Wxh1, Whh1, bxh1, bhh1, fc_w, fc_b, out);
}